// round 7
// baseline (speedup 1.0000x reference)
#include <cuda_runtime.h>

#define NUM_NODES 50000
#define C 64
#define NUM_EDGES 800000

// Scratch (allocation-free rule: __device__ globals)
__device__ __align__(16) float g_Wt[128 * 64];   // W transposed: [k][o]
__device__ int g_degi[NUM_NODES];    // per-destination degree (int)
__device__ int g_off[NUM_NODES];     // CSR start offsets
__device__ int g_cursor[NUM_NODES];  // build cursors (copy of offsets)
__device__ int g_srcs[NUM_EDGES];    // CSR: source node per slot

// ---------------------------------------------------------------------------
// Kernel 1: zero degree counters + transpose W. 196 blocks x 256.
// ---------------------------------------------------------------------------
__global__ void zero_kernel(const float* __restrict__ W) {
    int i = blockIdx.x * 256 + threadIdx.x;
    if (i < NUM_NODES) g_degi[i] = 0;
    if (i < 64 * 128) {
        int o = i >> 7;
        int k = i & 127;
        g_Wt[k * 64 + o] = W[i];
    }
}

// ---------------------------------------------------------------------------
// Kernel 2: histogram of destination nodes. Per-block dtype detection:
// a block's 256 int64-views of the ROW half (always in-bounds for both
// widths) are all in [0,NUM_NODES) iff the buffer is truly int64.
// Grid 3125 x 256 covers exactly NUM_EDGES.
// ---------------------------------------------------------------------------
__global__ void hist_kernel(const void* __restrict__ ei_raw) {
    int e = blockIdx.x * 256 + threadIdx.x;
    const long long* ei64 = (const long long*)ei_raw;
    long long rv = ei64[e];                       // row half: safe either way
    int is64 = __syncthreads_and(rv >= 0 && rv < NUM_NODES);

    long long c;
    if (is64) c = ei64[NUM_EDGES + e];
    else      c = ((const int*)ei_raw)[NUM_EDGES + e];
    if (c >= 0 && c < NUM_NODES) atomicAdd(&g_degi[(int)c], 1);
}

// ---------------------------------------------------------------------------
// Kernel 3: exclusive prefix sum of g_degi -> g_off, g_cursor.
// Single block, 1024 threads, 49 nodes per thread.
// ---------------------------------------------------------------------------
__global__ void scan_kernel() {
    const int CH = 49;
    __shared__ int wsum[32];
    int t = threadIdx.x;
    int lane = t & 31, wid = t >> 5;
    int base = t * CH;

    int s = 0;
    for (int i = 0; i < CH; i++) {
        int idx = base + i;
        if (idx < NUM_NODES) s += g_degi[idx];
    }
    // inclusive warp scan of per-thread sums
    int v = s;
    #pragma unroll
    for (int o = 1; o < 32; o <<= 1) {
        int u = __shfl_up_sync(0xFFFFFFFFu, v, o);
        if (lane >= o) v += u;
    }
    if (lane == 31) wsum[wid] = v;
    __syncthreads();
    if (wid == 0) {
        int w = wsum[lane];
        #pragma unroll
        for (int o = 1; o < 32; o <<= 1) {
            int u = __shfl_up_sync(0xFFFFFFFFu, w, o);
            if (lane >= o) w += u;
        }
        wsum[lane] = w;
    }
    __syncthreads();
    int excl = v - s + (wid > 0 ? wsum[wid - 1] : 0);

    int run = excl;
    for (int i = 0; i < CH; i++) {
        int idx = base + i;
        if (idx < NUM_NODES) {
            g_off[idx] = run;
            g_cursor[idx] = run;
            run += g_degi[idx];
        }
    }
}

// ---------------------------------------------------------------------------
// Kernel 4: CSR build — place each edge's source into its destination's slot.
// ---------------------------------------------------------------------------
__global__ void build_kernel(const void* __restrict__ ei_raw) {
    int e = blockIdx.x * 256 + threadIdx.x;
    const long long* ei64 = (const long long*)ei_raw;
    long long rv = ei64[e];
    int is64 = __syncthreads_and(rv >= 0 && rv < NUM_NODES);

    long long r, c;
    if (is64) { r = rv; c = ei64[NUM_EDGES + e]; }
    else {
        const int* ei = (const int*)ei_raw;
        r = ei[e];
        c = ei[NUM_EDGES + e];
    }
    if (c < 0 || c >= NUM_NODES) return;      // consistent with hist skip
    int rr = (int)r;
    if (rr < 0 || rr >= NUM_NODES) rr = 0;    // degrade, never crash
    int pos = atomicAdd(&g_cursor[(int)c], 1);
    g_srcs[pos] = rr;
}

// ---------------------------------------------------------------------------
// Kernel 5: FUSED gather + mean + concat-GEMM + bias.
// 64 nodes x 64 outs per 256-thread block.
// Phase A: stage x rows (F rows 0..63) + warp-per-8-nodes CSR gather into
//          F rows 64..127 (16 lanes per 256B row, 2 rows/warp in flight,
//          shfl_xor(16) combine).
// Phase B: register-tiled GEMM, thread = 1 node x 16 outs, fma.rn.f32x2.
// ---------------------------------------------------------------------------
#define F_STRIDE 65
#define FUSED_SMEM ((128 * 64 + 128 * F_STRIDE) * 4)   // 66048 B -> 3 CTAs/SM

__global__ void __launch_bounds__(256)
fused_kernel(const float* __restrict__ x,
             const float* __restrict__ b,
             float* __restrict__ out) {
    extern __shared__ float sm[];
    float* Wt = sm;                // [k][o] stride 64, k = 0..127
    float* F  = sm + 128 * 64;     // [c][n] stride 65

    int t = threadIdx.x;
    int base = blockIdx.x * 64;

    // Stage W (straight float4 copy, conflict-free)
    #pragma unroll
    for (int i = t; i < 128 * 64 / 4; i += 256)
        ((float4*)Wt)[i] = ((const float4*)g_Wt)[i];

    // Stage x rows -> F[0..63][*]  (coalesced LDG, conflict-free STS)
    #pragma unroll
    for (int i = t; i < 64 * 64; i += 256) {
        int nl = i >> 6;
        int c  = i & 63;
        int n  = base + nl;
        F[c * F_STRIDE + nl] = (n < NUM_NODES) ? x[n * C + c] : 0.f;
    }

    // CSR gather -> F[64..127][*]. Warp handles 8 nodes.
    {
        int wid = t >> 5, lane = t & 31;
        int half = lane >> 4;       // 0/1: even/odd edges
        int chunk = lane & 15;      // float4 chunk of the 256B row
        for (int j = 0; j < 8; j++) {
            int nl = wid * 8 + j;
            int n  = base + nl;
            float4 acc = make_float4(0.f, 0.f, 0.f, 0.f);
            int deg = 0;
            if (n < NUM_NODES) {
                int start = g_off[n];
                deg = g_degi[n];
                for (int e = half; e < deg; e += 2) {
                    int s = g_srcs[start + e];
                    float4 v = __ldg((const float4*)(x + s * C) + chunk);
                    acc.x += v.x; acc.y += v.y; acc.z += v.z; acc.w += v.w;
                }
            }
            acc.x += __shfl_xor_sync(0xFFFFFFFFu, acc.x, 16);
            acc.y += __shfl_xor_sync(0xFFFFFFFFu, acc.y, 16);
            acc.z += __shfl_xor_sync(0xFFFFFFFFu, acc.z, 16);
            acc.w += __shfl_xor_sync(0xFFFFFFFFu, acc.w, 16);
            float r = __frcp_rn(fmaxf((float)deg, 1.f));
            if (half == 0) {
                int c0 = 64 + (chunk << 2);
                F[(c0 + 0) * F_STRIDE + nl] = acc.x * r;
                F[(c0 + 1) * F_STRIDE + nl] = acc.y * r;
                F[(c0 + 2) * F_STRIDE + nl] = acc.z * r;
                F[(c0 + 3) * F_STRIDE + nl] = acc.w * r;
            }
        }
    }
    __syncthreads();

    // GEMM: thread = node nl x outputs [o0, o0+16)
    int nl = t & 63;
    int o0 = (t >> 6) << 4;   // 0,16,32,48 (warp-uniform)
    int n  = base + nl;

    unsigned long long acc[8];
    #pragma unroll
    for (int p = 0; p < 8; p++) acc[p] = 0ULL;

    const float* frow = F + nl;
    const float* wrow = Wt + o0;

    #pragma unroll 8
    for (int k = 0; k < 128; k++) {
        float f = frow[k * F_STRIDE];
        unsigned long long fp;
        asm("mov.b64 %0, {%1, %1};" : "=l"(fp) : "f"(f));
        const ulonglong2* wv = (const ulonglong2*)(wrow + k * 64);
        ulonglong2 w01 = wv[0];
        ulonglong2 w23 = wv[1];
        ulonglong2 w45 = wv[2];
        ulonglong2 w67 = wv[3];
        asm("fma.rn.f32x2 %0, %1, %2, %0;" : "+l"(acc[0]) : "l"(w01.x), "l"(fp));
        asm("fma.rn.f32x2 %0, %1, %2, %0;" : "+l"(acc[1]) : "l"(w01.y), "l"(fp));
        asm("fma.rn.f32x2 %0, %1, %2, %0;" : "+l"(acc[2]) : "l"(w23.x), "l"(fp));
        asm("fma.rn.f32x2 %0, %1, %2, %0;" : "+l"(acc[3]) : "l"(w23.y), "l"(fp));
        asm("fma.rn.f32x2 %0, %1, %2, %0;" : "+l"(acc[4]) : "l"(w45.x), "l"(fp));
        asm("fma.rn.f32x2 %0, %1, %2, %0;" : "+l"(acc[5]) : "l"(w45.y), "l"(fp));
        asm("fma.rn.f32x2 %0, %1, %2, %0;" : "+l"(acc[6]) : "l"(w67.x), "l"(fp));
        asm("fma.rn.f32x2 %0, %1, %2, %0;" : "+l"(acc[7]) : "l"(w67.y), "l"(fp));
    }

    if (n >= NUM_NODES) return;

    float* orow = out + n * C + o0;
    #pragma unroll
    for (int j = 0; j < 4; j++) {
        float lo0, hi0, lo1, hi1;
        asm("mov.b64 {%0, %1}, %2;" : "=f"(lo0), "=f"(hi0) : "l"(acc[2 * j]));
        asm("mov.b64 {%0, %1}, %2;" : "=f"(lo1), "=f"(hi1) : "l"(acc[2 * j + 1]));
        float4 r;
        r.x = lo0 + b[o0 + 4 * j + 0];
        r.y = hi0 + b[o0 + 4 * j + 1];
        r.z = lo1 + b[o0 + 4 * j + 2];
        r.w = hi1 + b[o0 + 4 * j + 3];
        *(float4*)(orow + 4 * j) = r;
    }
}

// ---------------------------------------------------------------------------
extern "C" void kernel_launch(void* const* d_in, const int* in_sizes, int n_in,
                              void* d_out, int out_size) {
    const float* x   = (const float*)d_in[0];
    const void*  ei  = d_in[1];
    const float* W   = (const float*)d_in[2];
    const float* b   = (const float*)d_in[3];
    float*       out = (float*)d_out;

    cudaFuncSetAttribute(fused_kernel,
                         cudaFuncAttributeMaxDynamicSharedMemorySize, FUSED_SMEM);

    zero_kernel<<<(NUM_NODES + 255) / 256, 256>>>(W);
    hist_kernel<<<NUM_EDGES / 256, 256>>>(ei);
    scan_kernel<<<1, 1024>>>();
    build_kernel<<<NUM_EDGES / 256, 256>>>(ei);
    fused_kernel<<<(NUM_NODES + 63) / 64, 256, FUSED_SMEM>>>(x, b, out);
}

// round 8
// speedup vs baseline: 1.3175x; 1.3175x over previous
#include <cuda_runtime.h>

#define NUM_NODES 50000
#define C 64
#define NUM_EDGES 800000
#define HALF_E (NUM_EDGES / 2)

// Scratch (allocation-free rule: __device__ globals)
__device__ __align__(16) float g_aggr[NUM_NODES * C];
__device__ float g_deg[NUM_NODES];
__device__ __align__(16) float g_Wt[128 * 64];   // W transposed: [k][o]
__device__ int g_is64;   // 1 if edge_index buffer is int64, 0 if int32

// ---------------------------------------------------------------------------
// Kernel 1: transpose W + detect index width. 32 blocks x 256.
// ---------------------------------------------------------------------------
__global__ void wprep_kernel(const float* __restrict__ W,
                             const long long* __restrict__ ei64) {
    int i = blockIdx.x * 256 + threadIdx.x;
    if (i < 64 * 128) {
        int o = i >> 7;
        int k = i & 127;
        g_Wt[k * 64 + o] = W[i];
    }
    if (blockIdx.x == 0) {
        __shared__ int bad;
        if (threadIdx.x == 0) bad = 0;
        __syncthreads();
        for (int j = threadIdx.x; j < 1024; j += 256) {
            long long v = ei64[j];
            if (v < 0 || v >= NUM_NODES) bad = 1;
        }
        __syncthreads();
        if (threadIdx.x == 0) g_is64 = bad ? 0 : 1;
    }
}

// ---------------------------------------------------------------------------
// Kernel 2: scatter-add x[row] into g_aggr[col], count degree.
// 16 lanes per edge (proven R4 layout), 2 edges per lane-group for MLP=2:
// group g handles edges g and g+HALF_E. Independent LDGs issued back-to-back.
// ---------------------------------------------------------------------------
__global__ void scatter_kernel(const float* __restrict__ x,
                               const void* __restrict__ ei_raw) {
    int idx = blockIdx.x * 256 + threadIdx.x;
    int g     = idx >> 4;        // edge-pair group: [0, HALF_E)
    int chunk = idx & 15;        // float4 chunk of the 256B row
    if (g >= HALF_E) return;
    int e0 = g, e1 = g + HALF_E;

    long long r0, c0, r1, c1;
    if (g_is64) {
        const long long* ei = (const long long*)ei_raw;
        r0 = __ldg(&ei[e0]); c0 = __ldg(&ei[NUM_EDGES + e0]);
        r1 = __ldg(&ei[e1]); c1 = __ldg(&ei[NUM_EDGES + e1]);
    } else {
        const int* ei = (const int*)ei_raw;
        r0 = __ldg(&ei[e0]); c0 = __ldg(&ei[NUM_EDGES + e0]);
        r1 = __ldg(&ei[e1]); c1 = __ldg(&ei[NUM_EDGES + e1]);
    }
    bool ok0 = (r0 >= 0 && r0 < NUM_NODES && c0 >= 0 && c0 < NUM_NODES);
    bool ok1 = (r1 >= 0 && r1 < NUM_NODES && c1 >= 0 && c1 < NUM_NODES);

    // Two independent gathers in flight (MLP=2); clamp bad rows to 0 so the
    // loads still issue unconditionally, results dropped by ok-guards.
    long long rr0 = ok0 ? r0 : 0, rr1 = ok1 ? r1 : 0;
    float4 v0 = __ldg(((const float4*)(x + rr0 * C)) + chunk);
    float4 v1 = __ldg(((const float4*)(x + rr1 * C)) + chunk);

    if (ok0) {
        float* dst = g_aggr + c0 * C + (chunk << 2);
        asm volatile("red.global.add.v4.f32 [%0], {%1,%2,%3,%4};"
                     :: "l"(dst), "f"(v0.x), "f"(v0.y), "f"(v0.z), "f"(v0.w)
                     : "memory");
        if (chunk == 0) atomicAdd(&g_deg[c0], 1.0f);
    }
    if (ok1) {
        float* dst = g_aggr + c1 * C + (chunk << 2);
        asm volatile("red.global.add.v4.f32 [%0], {%1,%2,%3,%4};"
                     :: "l"(dst), "f"(v1.x), "f"(v1.y), "f"(v1.z), "f"(v1.w)
                     : "memory");
        if (chunk == 0) atomicAdd(&g_deg[c1], 1.0f);
    }
}

// ---------------------------------------------------------------------------
// Kernel 3: out[n] = concat(x[n], aggr[n]*rdeg) @ W^T + b
// 512 threads, 64 nodes x 64 outs per block; thread = 1 node x 8 outs
// (4 f32x2 accumulators). W read via warp-uniform __ldg from g_Wt
// (L1-resident, broadcast) -> smem holds only F (33.5 KB) -> 3 CTAs/SM.
// ---------------------------------------------------------------------------
#define F_STRIDE 65
#define GEMM_SMEM ((128 * F_STRIDE + 64) * 4)   // 33536 B

__global__ void __launch_bounds__(512)
gemm_kernel(const float* __restrict__ x,
            const float* __restrict__ b,
            float* __restrict__ out) {
    extern __shared__ float sm[];
    float* F    = sm;                    // [c][n] stride 65, c = 0..127
    float* rdeg = sm + 128 * F_STRIDE;   // [64]

    int t = threadIdx.x;
    int base = blockIdx.x * 64;

    if (t < 64) {
        int n = base + t;
        rdeg[t] = (n < NUM_NODES) ? __frcp_rn(fmaxf(g_deg[n], 1.0f)) : 0.0f;
    }
    __syncthreads();

    // Stage features transposed: F[c][n]; coalesced gmem reads,
    // STS stride 65 -> conflict-free.
    #pragma unroll
    for (int i = t; i < 64 * 128; i += 512) {
        int nl = i >> 7;
        int c  = i & 127;
        int n  = base + nl;
        float v = 0.0f;
        if (n < NUM_NODES) {
            v = (c < C) ? x[n * C + c]
                        : g_aggr[n * C + (c - C)] * rdeg[nl];
        }
        F[c * F_STRIDE + nl] = v;
    }
    __syncthreads();

    int nl = t & 63;          // node within block
    int o0 = (t >> 6) << 3;   // output base: 0,8,..,56 (warp-uniform)
    int n  = base + nl;

    // 4 packed f32x2 accumulators = 8 outputs
    unsigned long long acc[4] = {0ULL, 0ULL, 0ULL, 0ULL};

    const float* frow = F + nl;
    const ulonglong2* wbase = (const ulonglong2*)(g_Wt + o0);

    #pragma unroll 8
    for (int k = 0; k < 128; k++) {
        float f = frow[k * F_STRIDE];
        unsigned long long fp;
        asm("mov.b64 %0, {%1, %1};" : "=l"(fp) : "f"(f));
        const ulonglong2* wp = (const ulonglong2*)((const float*)wbase + k * 64);
        ulonglong2 w01 = __ldg(wp);       // outs o0..o0+3
        ulonglong2 w23 = __ldg(wp + 1);   // outs o0+4..o0+7
        asm("fma.rn.f32x2 %0, %1, %2, %0;" : "+l"(acc[0]) : "l"(w01.x), "l"(fp));
        asm("fma.rn.f32x2 %0, %1, %2, %0;" : "+l"(acc[1]) : "l"(w01.y), "l"(fp));
        asm("fma.rn.f32x2 %0, %1, %2, %0;" : "+l"(acc[2]) : "l"(w23.x), "l"(fp));
        asm("fma.rn.f32x2 %0, %1, %2, %0;" : "+l"(acc[3]) : "l"(w23.y), "l"(fp));
    }

    if (n >= NUM_NODES) return;

    float* orow = out + n * C + o0;
    #pragma unroll
    for (int j = 0; j < 2; j++) {
        float lo0, hi0, lo1, hi1;
        asm("mov.b64 {%0, %1}, %2;" : "=f"(lo0), "=f"(hi0) : "l"(acc[2 * j]));
        asm("mov.b64 {%0, %1}, %2;" : "=f"(lo1), "=f"(hi1) : "l"(acc[2 * j + 1]));
        float4 r;
        r.x = lo0 + b[o0 + 4 * j + 0];
        r.y = hi0 + b[o0 + 4 * j + 1];
        r.z = lo1 + b[o0 + 4 * j + 2];
        r.w = hi1 + b[o0 + 4 * j + 3];
        *(float4*)(orow + 4 * j) = r;
    }
}

// ---------------------------------------------------------------------------
extern "C" void kernel_launch(void* const* d_in, const int* in_sizes, int n_in,
                              void* d_out, int out_size) {
    const float* x   = (const float*)d_in[0];
    const void*  ei  = d_in[1];
    const float* W   = (const float*)d_in[2];
    const float* b   = (const float*)d_in[3];
    float*       out = (float*)d_out;

    // Zero scratch via graph memset nodes (capture-legal, no allocation).
    void* aggr_ptr = nullptr;
    void* deg_ptr  = nullptr;
    cudaGetSymbolAddress(&aggr_ptr, g_aggr);
    cudaGetSymbolAddress(&deg_ptr, g_deg);
    cudaMemsetAsync(aggr_ptr, 0, NUM_NODES * C * sizeof(float));
    cudaMemsetAsync(deg_ptr, 0, NUM_NODES * sizeof(float));

    wprep_kernel<<<32, 256>>>(W, (const long long*)ei);
    scatter_kernel<<<(HALF_E * 16) / 256, 256>>>(x, ei);
    gemm_kernel<<<(NUM_NODES + 63) / 64, 512, GEMM_SMEM>>>(x, b, out);
}

// round 9
// speedup vs baseline: 1.5489x; 1.1757x over previous
#include <cuda_runtime.h>

#define NUM_NODES 50000
#define C 64
#define NUM_EDGES 800000

// Scratch (allocation-free rule: __device__ globals)
__device__ __align__(16) float g_aggr[NUM_NODES * C];
__device__ float g_deg[NUM_NODES];
__device__ __align__(16) float g_Wt[128 * 64];   // W transposed: [k][o]
__device__ int g_is64;   // 1 if edge_index buffer is int64, 0 if int32

// ---------------------------------------------------------------------------
// Kernel 1: transpose W + detect index width. 32 blocks x 256.
// ---------------------------------------------------------------------------
__global__ void wprep_kernel(const float* __restrict__ W,
                             const long long* __restrict__ ei64) {
    int i = blockIdx.x * 256 + threadIdx.x;
    if (i < 64 * 128) {
        int o = i >> 7;
        int k = i & 127;
        g_Wt[k * 64 + o] = W[i];
    }
    if (blockIdx.x == 0) {
        __shared__ int bad;
        if (threadIdx.x == 0) bad = 0;
        __syncthreads();
        for (int j = threadIdx.x; j < 1024; j += 256) {
            long long v = ei64[j];
            if (v < 0 || v >= NUM_NODES) bad = 1;
        }
        __syncthreads();
        if (threadIdx.x == 0) g_is64 = bad ? 0 : 1;
    }
}

// ---------------------------------------------------------------------------
// Kernel 2: scatter-add x[row] into g_aggr[col], count degree.
// Byte-exact R4 layout: 16 threads/edge, 1 float4 each,
// red.global.add.v4.f32 (no return trip). Measured 55.2 us.
// ---------------------------------------------------------------------------
__global__ void scatter_kernel(const float* __restrict__ x,
                               const void* __restrict__ ei_raw) {
    int idx = blockIdx.x * blockDim.x + threadIdx.x;
    if (idx >= NUM_EDGES * 16) return;
    int e     = idx >> 4;
    int chunk = idx & 15;

    long long r, c;
    if (g_is64) {
        const long long* ei = (const long long*)ei_raw;
        r = __ldg(&ei[e]);
        c = __ldg(&ei[NUM_EDGES + e]);
    } else {
        const int* ei = (const int*)ei_raw;
        r = __ldg(&ei[e]);
        c = __ldg(&ei[NUM_EDGES + e]);
    }
    if (r < 0 || r >= NUM_NODES || c < 0 || c >= NUM_NODES) return;

    float4 v = __ldg(((const float4*)(x + r * C)) + chunk);
    float* dst = g_aggr + c * C + (chunk << 2);
    asm volatile("red.global.add.v4.f32 [%0], {%1,%2,%3,%4};"
                 :: "l"(dst), "f"(v.x), "f"(v.y), "f"(v.z), "f"(v.w)
                 : "memory");
    if (chunk == 0) atomicAdd(&g_deg[c], 1.0f);
}

// ---------------------------------------------------------------------------
// Kernel 3 (R4 form): out[n] = concat(x[n], aggr[n]*rdeg) @ W^T + b
// Register-tiled: 64 nodes x 64 outs per 256-thread block.
// Thread = 1 node x 16 outputs (8 f32x2 accumulators, fma.rn.f32x2).
// Wt staged as straight float4 copy of pre-transposed g_Wt (stride 64,
// conflict-free); F[k][n] stride 65 (conflict-free both directions).
// ---------------------------------------------------------------------------
#define WT_STRIDE 64
#define F_STRIDE  65
#define SMEM_WT   0
#define SMEM_F    (128 * WT_STRIDE)                 // floats
#define SMEM_RD   (SMEM_F + 128 * F_STRIDE)         // floats
#define GEMM_SMEM ((SMEM_RD + 64) * 4)              // bytes = 66304

__global__ void __launch_bounds__(256, 3)
gemm_kernel(const float* __restrict__ x,
            const float* __restrict__ b,
            float* __restrict__ out) {
    extern __shared__ float sm[];
    float* Wt   = sm + SMEM_WT;   // [k][o] stride 64
    float* F    = sm + SMEM_F;    // [k][n] stride 65
    float* rdeg = sm + SMEM_RD;   // [64]

    int t = threadIdx.x;
    int base = blockIdx.x * 64;

    // Stage W: straight copy (coalesced LDG.128, conflict-free STS.128)
    #pragma unroll
    for (int i = t; i < 128 * 64 / 4; i += 256) {
        ((float4*)Wt)[i] = ((const float4*)g_Wt)[i];
    }

    // Per-node reciprocal degree
    if (t < 64) {
        int n = base + t;
        rdeg[t] = (n < NUM_NODES) ? __frcp_rn(fmaxf(g_deg[n], 1.0f)) : 0.0f;
    }
    __syncthreads();

    // Stage features transposed: F[c][n]; coalesced gmem reads,
    // STS stride 65 -> conflict-free.
    #pragma unroll
    for (int i = t; i < 64 * 128; i += 256) {
        int nl = i >> 7;
        int c  = i & 127;
        int n  = base + nl;
        float v = 0.0f;
        if (n < NUM_NODES) {
            v = (c < C) ? x[n * C + c]
                        : g_aggr[n * C + (c - C)] * rdeg[nl];
        }
        F[c * F_STRIDE + nl] = v;
    }
    __syncthreads();

    int nl = t & 63;          // node within block
    int o0 = (t >> 6) << 4;   // output base: 0,16,32,48 (warp-uniform)
    int n  = base + nl;

    // 8 packed f32x2 accumulators = 16 outputs
    unsigned long long acc[8];
    #pragma unroll
    for (int p = 0; p < 8; p++) acc[p] = 0ULL;

    const float* frow = F + nl;
    const float* wrow = Wt + o0;

    #pragma unroll 8
    for (int k = 0; k < 128; k++) {
        float f = frow[k * F_STRIDE];
        unsigned long long fp;
        asm("mov.b64 %0, {%1, %1};" : "=l"(fp) : "f"(f));
        const ulonglong2* wv = (const ulonglong2*)(wrow + k * WT_STRIDE);
        ulonglong2 w01 = wv[0];
        ulonglong2 w23 = wv[1];
        ulonglong2 w45 = wv[2];
        ulonglong2 w67 = wv[3];
        asm("fma.rn.f32x2 %0, %1, %2, %0;" : "+l"(acc[0]) : "l"(w01.x), "l"(fp));
        asm("fma.rn.f32x2 %0, %1, %2, %0;" : "+l"(acc[1]) : "l"(w01.y), "l"(fp));
        asm("fma.rn.f32x2 %0, %1, %2, %0;" : "+l"(acc[2]) : "l"(w23.x), "l"(fp));
        asm("fma.rn.f32x2 %0, %1, %2, %0;" : "+l"(acc[3]) : "l"(w23.y), "l"(fp));
        asm("fma.rn.f32x2 %0, %1, %2, %0;" : "+l"(acc[4]) : "l"(w45.x), "l"(fp));
        asm("fma.rn.f32x2 %0, %1, %2, %0;" : "+l"(acc[5]) : "l"(w45.y), "l"(fp));
        asm("fma.rn.f32x2 %0, %1, %2, %0;" : "+l"(acc[6]) : "l"(w67.x), "l"(fp));
        asm("fma.rn.f32x2 %0, %1, %2, %0;" : "+l"(acc[7]) : "l"(w67.y), "l"(fp));
    }

    if (n >= NUM_NODES) return;

    // Unpack, add bias, store as 4 x STG.128
    float* orow = out + n * 64 + o0;
    #pragma unroll
    for (int j = 0; j < 4; j++) {
        float lo0, hi0, lo1, hi1;
        asm("mov.b64 {%0, %1}, %2;" : "=f"(lo0), "=f"(hi0) : "l"(acc[2 * j]));
        asm("mov.b64 {%0, %1}, %2;" : "=f"(lo1), "=f"(hi1) : "l"(acc[2 * j + 1]));
        float4 r;
        r.x = lo0 + b[o0 + 4 * j + 0];
        r.y = hi0 + b[o0 + 4 * j + 1];
        r.z = lo1 + b[o0 + 4 * j + 2];
        r.w = hi1 + b[o0 + 4 * j + 3];
        *(float4*)(orow + 4 * j) = r;
    }
}

// ---------------------------------------------------------------------------
extern "C" void kernel_launch(void* const* d_in, const int* in_sizes, int n_in,
                              void* d_out, int out_size) {
    const float* x   = (const float*)d_in[0];
    const void*  ei  = d_in[1];
    const float* W   = (const float*)d_in[2];
    const float* b   = (const float*)d_in[3];
    float*       out = (float*)d_out;

    cudaFuncSetAttribute(gemm_kernel,
                         cudaFuncAttributeMaxDynamicSharedMemorySize, GEMM_SMEM);

    // Zero scratch via graph memset nodes (capture-legal, no allocation).
    void* aggr_ptr = nullptr;
    void* deg_ptr  = nullptr;
    cudaGetSymbolAddress(&aggr_ptr, g_aggr);
    cudaGetSymbolAddress(&deg_ptr, g_deg);
    cudaMemsetAsync(aggr_ptr, 0, NUM_NODES * C * sizeof(float));
    cudaMemsetAsync(deg_ptr, 0, NUM_NODES * sizeof(float));

    wprep_kernel<<<32, 256>>>(W, (const long long*)ei);
    scatter_kernel<<<(NUM_EDGES * 16) / 256, 256>>>(x, ei);
    gemm_kernel<<<(NUM_NODES + 63) / 64, 256, GEMM_SMEM>>>(x, b, out);
}